// round 1
// baseline (speedup 1.0000x reference)
#include <cuda_runtime.h>
#include <math.h>

// Problem constants
#define Bz 8
#define Tz 1024
#define Cz 768
#define NHz 12
#define HDz 64
#define Mz (Bz*Tz)        // 8192

// Scratch (device globals; no allocation)
__device__ float g_q[Bz*NHz*Tz*HDz];
__device__ float g_k[Bz*NHz*Tz*HDz];
__device__ float g_v[Bz*NHz*Tz*HDz];
__device__ float g_y[Bz*Tz*Cz];

// ---------------------------------------------------------------------------
// SGEMM 128x128x8, 256 threads, 8x8 microtile.
// EPI 0: QKV epilogue (scatter into g_q/g_k/g_v with head-major layout)
// EPI 1: proj epilogue (write C = acc + bias directly)
// ---------------------------------------------------------------------------
template <int EPI>
__global__ __launch_bounds__(256) void sgemm_kernel(
    const float* __restrict__ A, const float* __restrict__ Bm,
    const float* __restrict__ bias, float* __restrict__ Cout,
    int M, int N, int K)
{
    __shared__ float As[8][128];
    __shared__ float Bs[8][128];

    const int tid  = threadIdx.x;
    const int brow = blockIdx.y;
    const int bcol = blockIdx.x;
    const int tcol = tid & 15;   // 0..15
    const int trow = tid >> 4;   // 0..15

    const int aRow = tid >> 1;          // 0..127
    const int aCol = (tid & 1) * 4;     // 0 or 4
    const int bRow = tid >> 5;          // 0..7
    const int bCol = (tid & 31) * 4;    // 0..124

    const float* Aptr = A + (brow*128 + aRow)*K + aCol;
    const float* Bptr = Bm + bRow*N + bcol*128 + bCol;

    float acc[8][8];
#pragma unroll
    for (int i = 0; i < 8; ++i)
#pragma unroll
        for (int j = 0; j < 8; ++j) acc[i][j] = 0.f;

    for (int k0 = 0; k0 < K; k0 += 8) {
        float4 a4 = *(const float4*)(Aptr);  Aptr += 8;
        float4 b4 = *(const float4*)(Bptr);  Bptr += 8*N;

        As[aCol+0][aRow] = a4.x;
        As[aCol+1][aRow] = a4.y;
        As[aCol+2][aRow] = a4.z;
        As[aCol+3][aRow] = a4.w;
        *(float4*)&Bs[bRow][bCol] = b4;
        __syncthreads();

#pragma unroll
        for (int kk = 0; kk < 8; ++kk) {
            float rm[8], rn[8];
#pragma unroll
            for (int i = 0; i < 8; ++i) rm[i] = As[kk][trow*8 + i];
#pragma unroll
            for (int j = 0; j < 8; ++j) rn[j] = Bs[kk][tcol*8 + j];
#pragma unroll
            for (int i = 0; i < 8; ++i)
#pragma unroll
                for (int j = 0; j < 8; ++j)
                    acc[i][j] += rm[i] * rn[j];
        }
        __syncthreads();
    }

#pragma unroll
    for (int i = 0; i < 8; ++i) {
        const int m = brow*128 + trow*8 + i;
#pragma unroll
        for (int j = 0; j < 8; ++j) {
            const int n = bcol*128 + tcol*8 + j;
            const float val = acc[i][j] + bias[n];
            if (EPI == 0) {
                // n in [0,3C): which 0=q 1=k 2=v
                const int which = n / Cz;
                const int c = n - which * Cz;
                const int h = c >> 6;       // /HD
                const int d = c & 63;       // %HD
                const int b = m >> 10;      // /T
                const int t = m & 1023;     // %T
                float* dst = (which == 0) ? g_q : (which == 1) ? g_k : g_v;
                dst[(((b*NHz + h) << 10) + t)*HDz + d] = val;
            } else {
                Cout[m*N + n] = val;
            }
        }
    }
}

// ---------------------------------------------------------------------------
// Flash attention, fp32. Block: 64 queries x HD=64, tiles of 64 keys.
// 256 threads; each thread owns a 4x4 microtile of S (and of O).
// Causal: only key tiles kt <= qb are visited; mask applied on diagonal tile.
// Dynamic smem: Qs[64][65] (d-major), Ks[64][65] (d-major),
//               Vs[64][65] (k-major), Ss[64][65] (q-major)  => 66,560 B
// ---------------------------------------------------------------------------
__global__ __launch_bounds__(256) void flash_kernel(
    const float* __restrict__ gq, const float* __restrict__ gk,
    const float* __restrict__ gv, float* __restrict__ gy)
{
    extern __shared__ float sm[];
    float* Qs = sm;                 // [64][65], Qs[d*65 + q]
    float* Ks = Qs + 64*65;         // [64][65], Ks[d*65 + k]
    float* Vs = Ks + 64*65;         // [64][65], Vs[k*65 + d]
    float* Ss = Vs + 64*65;         // [64][65], Ss[q*65 + k]
    __shared__ float m_s[64], l_s[64], alpha_s[64];

    const int bh  = blockIdx.y;       // 0..B*NH-1
    const int qb  = blockIdx.x;       // 0..T/64-1
    const int tid = threadIdx.x;
    const int tx  = tid & 15;         // key/dim microtile col group
    const int ty  = tid >> 4;         // query microtile row group
    const int wid = tid >> 5, lane = tid & 31;

    const float scale = 0.125f;       // 1/sqrt(64)

    const float* qbase = gq + ((size_t)bh*Tz + qb*64) * HDz;

    // Load Q transposed (d-major)
    for (int i = tid; i < 64*16; i += 256) {
        const int q  = i >> 4;
        const int db = (i & 15) * 4;
        float4 v4 = *(const float4*)(qbase + q*HDz + db);
        Qs[(db+0)*65 + q] = v4.x;
        Qs[(db+1)*65 + q] = v4.y;
        Qs[(db+2)*65 + q] = v4.z;
        Qs[(db+3)*65 + q] = v4.w;
    }
    if (tid < 64) { m_s[tid] = -INFINITY; l_s[tid] = 0.f; }

    float O[4][4];
#pragma unroll
    for (int i = 0; i < 4; ++i)
#pragma unroll
        for (int j = 0; j < 4; ++j) O[i][j] = 0.f;

    const int ntiles = qb + 1;
    for (int kt = 0; kt < ntiles; ++kt) {
        const float* kbase = gk + ((size_t)bh*Tz + kt*64) * HDz;
        const float* vbase = gv + ((size_t)bh*Tz + kt*64) * HDz;

        __syncthreads();  // previous iteration done with Ks/Vs/Ss
        for (int i = tid; i < 64*16; i += 256) {
            const int r  = i >> 4;
            const int db = (i & 15) * 4;
            float4 k4 = *(const float4*)(kbase + r*HDz + db);
            Ks[(db+0)*65 + r] = k4.x;
            Ks[(db+1)*65 + r] = k4.y;
            Ks[(db+2)*65 + r] = k4.z;
            Ks[(db+3)*65 + r] = k4.w;
            float4 v4 = *(const float4*)(vbase + r*HDz + db);
            Vs[r*65 + db+0] = v4.x;
            Vs[r*65 + db+1] = v4.y;
            Vs[r*65 + db+2] = v4.z;
            Vs[r*65 + db+3] = v4.w;
        }
        __syncthreads();

        // S = Q K^T  (64x64x64)
        float acc[4][4];
#pragma unroll
        for (int i = 0; i < 4; ++i)
#pragma unroll
            for (int j = 0; j < 4; ++j) acc[i][j] = 0.f;

#pragma unroll 8
        for (int d = 0; d < 64; ++d) {
            float a[4], b[4];
#pragma unroll
            for (int i = 0; i < 4; ++i) a[i] = Qs[d*65 + ty*4 + i];
#pragma unroll
            for (int j = 0; j < 4; ++j) b[j] = Ks[d*65 + tx*4 + j];
#pragma unroll
            for (int i = 0; i < 4; ++i)
#pragma unroll
                for (int j = 0; j < 4; ++j)
                    acc[i][j] += a[i] * b[j];
        }

        const bool diag = (kt == qb);
#pragma unroll
        for (int i = 0; i < 4; ++i)
#pragma unroll
            for (int j = 0; j < 4; ++j) {
                float s = acc[i][j] * scale;
                if (diag && (tx*4 + j) > (ty*4 + i)) s = -INFINITY;
                Ss[(ty*4 + i)*65 + tx*4 + j] = s;
            }
        __syncthreads();

        // Online softmax: warp w handles rows 8w..8w+7
#pragma unroll
        for (int rr = 0; rr < 8; ++rr) {
            const int r = wid*8 + rr;
            float s0 = Ss[r*65 + lane];
            float s1 = Ss[r*65 + 32 + lane];
            float mx = fmaxf(s0, s1);
#pragma unroll
            for (int off = 16; off > 0; off >>= 1)
                mx = fmaxf(mx, __shfl_xor_sync(0xffffffffu, mx, off));
            const float mprev = m_s[r];
            const float mnew  = fmaxf(mprev, mx);
            const float p0 = __expf(s0 - mnew);
            const float p1 = __expf(s1 - mnew);
            Ss[r*65 + lane]      = p0;
            Ss[r*65 + 32 + lane] = p1;
            float sum = p0 + p1;
#pragma unroll
            for (int off = 16; off > 0; off >>= 1)
                sum += __shfl_xor_sync(0xffffffffu, sum, off);
            if (lane == 0) {
                const float al = __expf(mprev - mnew);
                alpha_s[r] = al;
                l_s[r] = l_s[r]*al + sum;
                m_s[r] = mnew;
            }
        }
        __syncthreads();

        // O = O*alpha + P V  (64x64x64)
        float al[4];
#pragma unroll
        for (int i = 0; i < 4; ++i) al[i] = alpha_s[ty*4 + i];
#pragma unroll
        for (int i = 0; i < 4; ++i)
#pragma unroll
            for (int j = 0; j < 4; ++j) O[i][j] *= al[i];

#pragma unroll 8
        for (int k = 0; k < 64; ++k) {
            float p[4], v[4];
#pragma unroll
            for (int i = 0; i < 4; ++i) p[i] = Ss[(ty*4 + i)*65 + k];
#pragma unroll
            for (int j = 0; j < 4; ++j) v[j] = Vs[k*65 + tx*4 + j];
#pragma unroll
            for (int i = 0; i < 4; ++i)
#pragma unroll
                for (int j = 0; j < 4; ++j)
                    O[i][j] += p[i] * v[j];
        }
    }

    // Epilogue: y[b, t, h*HD + d] = O / l
    const int b = bh / NHz;
    const int h = bh % NHz;
#pragma unroll
    for (int i = 0; i < 4; ++i) {
        const int q   = qb*64 + ty*4 + i;
        const float inv = 1.f / l_s[ty*4 + i];
#pragma unroll
        for (int j = 0; j < 4; ++j) {
            gy[((size_t)b*Tz + q)*Cz + h*HDz + tx*4 + j] = O[i][j] * inv;
        }
    }
}

// ---------------------------------------------------------------------------
extern "C" void kernel_launch(void* const* d_in, const int* in_sizes, int n_in,
                              void* d_out, int out_size)
{
    (void)in_sizes; (void)n_in; (void)out_size;
    const float* x      = (const float*)d_in[0];
    const float* w_attn = (const float*)d_in[1];
    const float* b_attn = (const float*)d_in[2];
    const float* w_proj = (const float*)d_in[3];
    const float* b_proj = (const float*)d_in[4];
    float* out = (float*)d_out;

    float *pq, *pk, *pv, *py;
    cudaGetSymbolAddress((void**)&pq, g_q);
    cudaGetSymbolAddress((void**)&pk, g_k);
    cudaGetSymbolAddress((void**)&pv, g_v);
    cudaGetSymbolAddress((void**)&py, g_y);

    const int flash_smem = 4 * 64 * 65 * (int)sizeof(float);  // 66,560 B
    cudaFuncSetAttribute(flash_kernel,
                         cudaFuncAttributeMaxDynamicSharedMemorySize,
                         flash_smem);

    // 1) QKV = x @ w_attn + b_attn, scattered into g_q/g_k/g_v
    {
        dim3 grid(3*Cz/128, Mz/128);   // (18, 64)
        sgemm_kernel<0><<<grid, 256>>>(x, w_attn, b_attn, nullptr,
                                       Mz, 3*Cz, Cz);
    }
    // 2) Flash attention into g_y
    {
        dim3 grid(Tz/64, Bz*NHz);      // (16, 96)
        flash_kernel<<<grid, 256, flash_smem>>>(pq, pk, pv, py);
    }
    // 3) out = g_y @ w_proj + b_proj
    {
        dim3 grid(Cz/128, Mz/128);     // (6, 64)
        sgemm_kernel<1><<<grid, 256>>>(py, w_proj, b_proj, out,
                                       Mz, Cz, Cz);
    }
}

// round 2
// speedup vs baseline: 1.8000x; 1.8000x over previous
#include <cuda_runtime.h>
#include <math.h>
#include <stdint.h>

// Problem constants
#define Bz 8
#define Tz 1024
#define Cz 768
#define NHz 12
#define HDz 64
#define Mz (Bz*Tz)        // 8192

// Scratch (device globals; no allocation)
__device__ float g_q[Bz*NHz*Tz*HDz];
__device__ float g_k[Bz*NHz*Tz*HDz];
__device__ float g_v[Bz*NHz*Tz*HDz];
__device__ float g_y[Bz*Tz*Cz];

__device__ __forceinline__ uint32_t f2tf32(float f) {
    uint32_t u;
    asm("cvt.rna.tf32.f32 %0, %1;" : "=r"(u) : "f"(f));
    return u;
}

// ---------------------------------------------------------------------------
// TF32 tensor-core GEMM, 128x128 CTA tile, K-stage 16, double-buffered smem.
// 8 warps in a 2(m) x 4(n) grid; warp tile 64x32 = 4x4 m16n8k8 mma tiles.
// EPI 0: QKV epilogue (scatter into g_q/g_k/g_v head-major)
// EPI 1: proj epilogue (C = acc + bias)
// ---------------------------------------------------------------------------
#define ASTRIDE 20    // 16 k + pad (conflict-free frag loads)
#define BSTRIDE 132   // 128 n + pad

template <int EPI>
__global__ __launch_bounds__(256) void tgemm_kernel(
    const float* __restrict__ A, const float* __restrict__ Bm,
    const float* __restrict__ bias, float* __restrict__ Cout,
    int M, int N, int K)
{
    __shared__ float As[2][128*ASTRIDE];
    __shared__ float Bs[2][16*BSTRIDE];

    const int tid  = threadIdx.x;
    const int wid  = tid >> 5;
    const int lane = tid & 31;
    const int wm   = wid & 1;          // 0..1
    const int wn   = wid >> 1;         // 0..3
    const int gr   = lane >> 2;        // 0..7
    const int tig  = lane & 3;         // 0..3
    const int bm   = blockIdx.y * 128;
    const int bn   = blockIdx.x * 128;

    // Producer indices
    const int aRow0 = tid >> 2;            // 0..63 (second load: +64)
    const int aKc   = (tid & 3) * 4;       // 0,4,8,12
    const int bK0   = tid >> 5;            // 0..7 (second: +8)
    const int bNc   = (tid & 31) * 4;      // 0..124

    const float* Ap0 = A + (size_t)(bm + aRow0)      * K + aKc;
    const float* Ap1 = A + (size_t)(bm + aRow0 + 64) * K + aKc;
    const float* Bp0 = Bm + (size_t)bK0       * N + bn + bNc;
    const float* Bp1 = Bm + (size_t)(bK0 + 8) * N + bn + bNc;

    float acc[4][4][4];
#pragma unroll
    for (int i = 0; i < 4; ++i)
#pragma unroll
        for (int j = 0; j < 4; ++j)
#pragma unroll
            for (int r = 0; r < 4; ++r) acc[i][j][r] = 0.f;

    const int nstages = K / 16;

    // Prologue: stage 0 -> smem buf 0
    {
        float4 a0 = *(const float4*)(Ap0);
        float4 a1 = *(const float4*)(Ap1);
        float4 b0 = *(const float4*)(Bp0);
        float4 b1 = *(const float4*)(Bp1);
        uint32_t* AsU = (uint32_t*)As[0];
        uint32_t* BsU = (uint32_t*)Bs[0];
        AsU[aRow0*ASTRIDE + aKc + 0] = f2tf32(a0.x);
        AsU[aRow0*ASTRIDE + aKc + 1] = f2tf32(a0.y);
        AsU[aRow0*ASTRIDE + aKc + 2] = f2tf32(a0.z);
        AsU[aRow0*ASTRIDE + aKc + 3] = f2tf32(a0.w);
        AsU[(aRow0+64)*ASTRIDE + aKc + 0] = f2tf32(a1.x);
        AsU[(aRow0+64)*ASTRIDE + aKc + 1] = f2tf32(a1.y);
        AsU[(aRow0+64)*ASTRIDE + aKc + 2] = f2tf32(a1.z);
        AsU[(aRow0+64)*ASTRIDE + aKc + 3] = f2tf32(a1.w);
        BsU[bK0*BSTRIDE + bNc + 0] = f2tf32(b0.x);
        BsU[bK0*BSTRIDE + bNc + 1] = f2tf32(b0.y);
        BsU[bK0*BSTRIDE + bNc + 2] = f2tf32(b0.z);
        BsU[bK0*BSTRIDE + bNc + 3] = f2tf32(b0.w);
        BsU[(bK0+8)*BSTRIDE + bNc + 0] = f2tf32(b1.x);
        BsU[(bK0+8)*BSTRIDE + bNc + 1] = f2tf32(b1.y);
        BsU[(bK0+8)*BSTRIDE + bNc + 2] = f2tf32(b1.z);
        BsU[(bK0+8)*BSTRIDE + bNc + 3] = f2tf32(b1.w);
    }
    __syncthreads();

    int buf = 0;
    for (int s = 0; s < nstages; ++s) {
        float4 a0, a1, b0, b1;
        const bool more = (s + 1 < nstages);
        if (more) {
            const int ko = (s + 1) * 16;
            a0 = *(const float4*)(Ap0 + ko);
            a1 = *(const float4*)(Ap1 + ko);
            b0 = *(const float4*)(Bp0 + (size_t)ko * N);
            b1 = *(const float4*)(Bp1 + (size_t)ko * N);
        }

        // Compute on current buffer
        const float* Asb = As[buf];
        const float* Bsb = Bs[buf];
#pragma unroll
        for (int ks = 0; ks < 2; ++ks) {
            const int kb = ks * 8;
            uint32_t af[4][4];
#pragma unroll
            for (int mt = 0; mt < 4; ++mt) {
                const int r = wm*64 + mt*16 + gr;
                af[mt][0] = __float_as_uint(Asb[ r     *ASTRIDE + kb + tig    ]);
                af[mt][1] = __float_as_uint(Asb[(r + 8)*ASTRIDE + kb + tig    ]);
                af[mt][2] = __float_as_uint(Asb[ r     *ASTRIDE + kb + tig + 4]);
                af[mt][3] = __float_as_uint(Asb[(r + 8)*ASTRIDE + kb + tig + 4]);
            }
            uint32_t bf[4][2];
#pragma unroll
            for (int nt = 0; nt < 4; ++nt) {
                const int n = wn*32 + nt*8 + gr;
                bf[nt][0] = __float_as_uint(Bsb[(kb + tig    )*BSTRIDE + n]);
                bf[nt][1] = __float_as_uint(Bsb[(kb + tig + 4)*BSTRIDE + n]);
            }
#pragma unroll
            for (int mt = 0; mt < 4; ++mt)
#pragma unroll
                for (int nt = 0; nt < 4; ++nt) {
                    asm volatile(
                        "mma.sync.aligned.m16n8k8.row.col.f32.tf32.tf32.f32 "
                        "{%0,%1,%2,%3}, {%4,%5,%6,%7}, {%8,%9}, {%0,%1,%2,%3};\n"
                        : "+f"(acc[mt][nt][0]), "+f"(acc[mt][nt][1]),
                          "+f"(acc[mt][nt][2]), "+f"(acc[mt][nt][3])
                        : "r"(af[mt][0]), "r"(af[mt][1]),
                          "r"(af[mt][2]), "r"(af[mt][3]),
                          "r"(bf[nt][0]), "r"(bf[nt][1]));
                }
        }

        if (more) {
            __syncthreads();   // all warps done reading buf^1 (stage s-1)
            const int nb = buf ^ 1;
            uint32_t* AsU = (uint32_t*)As[nb];
            uint32_t* BsU = (uint32_t*)Bs[nb];
            AsU[aRow0*ASTRIDE + aKc + 0] = f2tf32(a0.x);
            AsU[aRow0*ASTRIDE + aKc + 1] = f2tf32(a0.y);
            AsU[aRow0*ASTRIDE + aKc + 2] = f2tf32(a0.z);
            AsU[aRow0*ASTRIDE + aKc + 3] = f2tf32(a0.w);
            AsU[(aRow0+64)*ASTRIDE + aKc + 0] = f2tf32(a1.x);
            AsU[(aRow0+64)*ASTRIDE + aKc + 1] = f2tf32(a1.y);
            AsU[(aRow0+64)*ASTRIDE + aKc + 2] = f2tf32(a1.z);
            AsU[(aRow0+64)*ASTRIDE + aKc + 3] = f2tf32(a1.w);
            BsU[bK0*BSTRIDE + bNc + 0] = f2tf32(b0.x);
            BsU[bK0*BSTRIDE + bNc + 1] = f2tf32(b0.y);
            BsU[bK0*BSTRIDE + bNc + 2] = f2tf32(b0.z);
            BsU[bK0*BSTRIDE + bNc + 3] = f2tf32(b0.w);
            BsU[(bK0+8)*BSTRIDE + bNc + 0] = f2tf32(b1.x);
            BsU[(bK0+8)*BSTRIDE + bNc + 1] = f2tf32(b1.y);
            BsU[(bK0+8)*BSTRIDE + bNc + 2] = f2tf32(b1.z);
            BsU[(bK0+8)*BSTRIDE + bNc + 3] = f2tf32(b1.w);
            __syncthreads();
            buf = nb;
        }
    }

    // Epilogue
#pragma unroll
    for (int mt = 0; mt < 4; ++mt) {
#pragma unroll
        for (int nt = 0; nt < 4; ++nt) {
            const int nb2 = bn + wn*32 + nt*8 + 2*tig;   // even
#pragma unroll
            for (int half = 0; half < 2; ++half) {       // rows gr, gr+8
                const int m = bm + wm*64 + mt*16 + gr + half*8;
                const float v0 = acc[mt][nt][half*2 + 0] + bias[nb2 + 0];
                const float v1 = acc[mt][nt][half*2 + 1] + bias[nb2 + 1];
                if (EPI == 0) {
                    const int which = nb2 / Cz;          // 0=q 1=k 2=v
                    const int c = nb2 - which * Cz;
                    const int h = c >> 6;
                    const int d = c & 63;                // even; d+1 same head
                    const int b = m >> 10;
                    const int t = m & 1023;
                    float* dst = (which == 0) ? g_q : (which == 1) ? g_k : g_v;
                    float2 val = make_float2(v0, v1);
                    *(float2*)&dst[(((size_t)(b*NHz + h) << 10) + t)*HDz + d] = val;
                } else {
                    float2 val = make_float2(v0, v1);
                    *(float2*)&Cout[(size_t)m*N + nb2] = val;
                }
            }
        }
    }
}

// ---------------------------------------------------------------------------
// Flash attention, fp32 (unchanged from R1). 64q x 64k tiles, online softmax.
// ---------------------------------------------------------------------------
__global__ __launch_bounds__(256) void flash_kernel(
    const float* __restrict__ gq, const float* __restrict__ gk,
    const float* __restrict__ gv, float* __restrict__ gy)
{
    extern __shared__ float sm[];
    float* Qs = sm;                 // [64][65], Qs[d*65 + q]
    float* Ks = Qs + 64*65;         // [64][65], Ks[d*65 + k]
    float* Vs = Ks + 64*65;         // [64][65], Vs[k*65 + d]
    float* Ss = Vs + 64*65;         // [64][65], Ss[q*65 + k]
    __shared__ float m_s[64], l_s[64], alpha_s[64];

    const int bh  = blockIdx.y;
    const int qb  = blockIdx.x;
    const int tid = threadIdx.x;
    const int tx  = tid & 15;
    const int ty  = tid >> 4;
    const int wid = tid >> 5, lane = tid & 31;

    const float scale = 0.125f;

    const float* qbase = gq + ((size_t)bh*Tz + qb*64) * HDz;

    for (int i = tid; i < 64*16; i += 256) {
        const int q  = i >> 4;
        const int db = (i & 15) * 4;
        float4 v4 = *(const float4*)(qbase + q*HDz + db);
        Qs[(db+0)*65 + q] = v4.x;
        Qs[(db+1)*65 + q] = v4.y;
        Qs[(db+2)*65 + q] = v4.z;
        Qs[(db+3)*65 + q] = v4.w;
    }
    if (tid < 64) { m_s[tid] = -INFINITY; l_s[tid] = 0.f; }

    float O[4][4];
#pragma unroll
    for (int i = 0; i < 4; ++i)
#pragma unroll
        for (int j = 0; j < 4; ++j) O[i][j] = 0.f;

    const int ntiles = qb + 1;
    for (int kt = 0; kt < ntiles; ++kt) {
        const float* kbase = gk + ((size_t)bh*Tz + kt*64) * HDz;
        const float* vbase = gv + ((size_t)bh*Tz + kt*64) * HDz;

        __syncthreads();
        for (int i = tid; i < 64*16; i += 256) {
            const int r  = i >> 4;
            const int db = (i & 15) * 4;
            float4 k4 = *(const float4*)(kbase + r*HDz + db);
            Ks[(db+0)*65 + r] = k4.x;
            Ks[(db+1)*65 + r] = k4.y;
            Ks[(db+2)*65 + r] = k4.z;
            Ks[(db+3)*65 + r] = k4.w;
            float4 v4 = *(const float4*)(vbase + r*HDz + db);
            Vs[r*65 + db+0] = v4.x;
            Vs[r*65 + db+1] = v4.y;
            Vs[r*65 + db+2] = v4.z;
            Vs[r*65 + db+3] = v4.w;
        }
        __syncthreads();

        float acc[4][4];
#pragma unroll
        for (int i = 0; i < 4; ++i)
#pragma unroll
            for (int j = 0; j < 4; ++j) acc[i][j] = 0.f;

#pragma unroll 8
        for (int d = 0; d < 64; ++d) {
            float a[4], b[4];
#pragma unroll
            for (int i = 0; i < 4; ++i) a[i] = Qs[d*65 + ty*4 + i];
#pragma unroll
            for (int j = 0; j < 4; ++j) b[j] = Ks[d*65 + tx*4 + j];
#pragma unroll
            for (int i = 0; i < 4; ++i)
#pragma unroll
                for (int j = 0; j < 4; ++j)
                    acc[i][j] += a[i] * b[j];
        }

        const bool diag = (kt == qb);
#pragma unroll
        for (int i = 0; i < 4; ++i)
#pragma unroll
            for (int j = 0; j < 4; ++j) {
                float s = acc[i][j] * scale;
                if (diag && (tx*4 + j) > (ty*4 + i)) s = -INFINITY;
                Ss[(ty*4 + i)*65 + tx*4 + j] = s;
            }
        __syncthreads();

#pragma unroll
        for (int rr = 0; rr < 8; ++rr) {
            const int r = wid*8 + rr;
            float s0 = Ss[r*65 + lane];
            float s1 = Ss[r*65 + 32 + lane];
            float mx = fmaxf(s0, s1);
#pragma unroll
            for (int off = 16; off > 0; off >>= 1)
                mx = fmaxf(mx, __shfl_xor_sync(0xffffffffu, mx, off));
            const float mprev = m_s[r];
            const float mnew  = fmaxf(mprev, mx);
            const float p0 = __expf(s0 - mnew);
            const float p1 = __expf(s1 - mnew);
            Ss[r*65 + lane]      = p0;
            Ss[r*65 + 32 + lane] = p1;
            float sum = p0 + p1;
#pragma unroll
            for (int off = 16; off > 0; off >>= 1)
                sum += __shfl_xor_sync(0xffffffffu, sum, off);
            if (lane == 0) {
                const float al = __expf(mprev - mnew);
                alpha_s[r] = al;
                l_s[r] = l_s[r]*al + sum;
                m_s[r] = mnew;
            }
        }
        __syncthreads();

        float al[4];
#pragma unroll
        for (int i = 0; i < 4; ++i) al[i] = alpha_s[ty*4 + i];
#pragma unroll
        for (int i = 0; i < 4; ++i)
#pragma unroll
            for (int j = 0; j < 4; ++j) O[i][j] *= al[i];

#pragma unroll 8
        for (int k = 0; k < 64; ++k) {
            float p[4], v[4];
#pragma unroll
            for (int i = 0; i < 4; ++i) p[i] = Ss[(ty*4 + i)*65 + k];
#pragma unroll
            for (int j = 0; j < 4; ++j) v[j] = Vs[k*65 + tx*4 + j];
#pragma unroll
            for (int i = 0; i < 4; ++i)
#pragma unroll
                for (int j = 0; j < 4; ++j)
                    O[i][j] += p[i] * v[j];
        }
    }

    const int b = bh / NHz;
    const int h = bh % NHz;
#pragma unroll
    for (int i = 0; i < 4; ++i) {
        const int q   = qb*64 + ty*4 + i;
        const float inv = 1.f / l_s[ty*4 + i];
#pragma unroll
        for (int j = 0; j < 4; ++j) {
            gy[((size_t)b*Tz + q)*Cz + h*HDz + tx*4 + j] = O[i][j] * inv;
        }
    }
}

// ---------------------------------------------------------------------------
extern "C" void kernel_launch(void* const* d_in, const int* in_sizes, int n_in,
                              void* d_out, int out_size)
{
    (void)in_sizes; (void)n_in; (void)out_size;
    const float* x      = (const float*)d_in[0];
    const float* w_attn = (const float*)d_in[1];
    const float* b_attn = (const float*)d_in[2];
    const float* w_proj = (const float*)d_in[3];
    const float* b_proj = (const float*)d_in[4];
    float* out = (float*)d_out;

    float *pq, *pk, *pv, *py;
    cudaGetSymbolAddress((void**)&pq, g_q);
    cudaGetSymbolAddress((void**)&pk, g_k);
    cudaGetSymbolAddress((void**)&pv, g_v);
    cudaGetSymbolAddress((void**)&py, g_y);

    const int flash_smem = 4 * 64 * 65 * (int)sizeof(float);  // 66,560 B
    cudaFuncSetAttribute(flash_kernel,
                         cudaFuncAttributeMaxDynamicSharedMemorySize,
                         flash_smem);

    // 1) QKV = x @ w_attn + b_attn (tf32 tensor cores), scatter to g_q/g_k/g_v
    {
        dim3 grid(3*Cz/128, Mz/128);   // (18, 64)
        tgemm_kernel<0><<<grid, 256>>>(x, w_attn, b_attn, nullptr,
                                       Mz, 3*Cz, Cz);
    }
    // 2) Flash attention into g_y
    {
        dim3 grid(Tz/64, Bz*NHz);      // (16, 96)
        flash_kernel<<<grid, 256, flash_smem>>>(pq, pk, pv, py);
    }
    // 3) out = g_y @ w_proj + b_proj (tf32 tensor cores)
    {
        dim3 grid(Cz/128, Mz/128);     // (6, 64)
        tgemm_kernel<1><<<grid, 256>>>(py, w_proj, b_proj, out,
                                       Mz, Cz, Cz);
    }
}

// round 3
// speedup vs baseline: 2.4393x; 1.3552x over previous
#include <cuda_runtime.h>
#include <math.h>
#include <stdint.h>

// Problem constants
#define Bz 8
#define Tz 1024
#define Cz 768
#define NHz 12
#define HDz 64
#define Mz (Bz*Tz)        // 8192

// Scratch (device globals; no allocation)
__device__ float g_q[Bz*NHz*Tz*HDz];
__device__ float g_k[Bz*NHz*Tz*HDz];
__device__ float g_v[Bz*NHz*Tz*HDz];
__device__ float g_y[Bz*Tz*Cz];

__device__ __forceinline__ uint32_t f2tf32(float f) {
    uint32_t u;
    asm("cvt.rna.tf32.f32 %0, %1;" : "=r"(u) : "f"(f));
    return u;
}

__device__ __forceinline__ void mma_tf32(
    float& d0, float& d1, float& d2, float& d3,
    uint32_t a0, uint32_t a1, uint32_t a2, uint32_t a3,
    uint32_t b0, uint32_t b1)
{
    asm volatile(
        "mma.sync.aligned.m16n8k8.row.col.f32.tf32.tf32.f32 "
        "{%0,%1,%2,%3}, {%4,%5,%6,%7}, {%8,%9}, {%0,%1,%2,%3};\n"
        : "+f"(d0), "+f"(d1), "+f"(d2), "+f"(d3)
        : "r"(a0), "r"(a1), "r"(a2), "r"(a3), "r"(b0), "r"(b1));
}

// ---------------------------------------------------------------------------
// TF32 tensor-core GEMM, 128x128 CTA tile, K-stage 16, double-buffered smem.
// (unchanged from R2)
// ---------------------------------------------------------------------------
#define ASTRIDE 20
#define BSTRIDE 132

template <int EPI>
__global__ __launch_bounds__(256) void tgemm_kernel(
    const float* __restrict__ A, const float* __restrict__ Bm,
    const float* __restrict__ bias, float* __restrict__ Cout,
    int M, int N, int K)
{
    __shared__ float As[2][128*ASTRIDE];
    __shared__ float Bs[2][16*BSTRIDE];

    const int tid  = threadIdx.x;
    const int wid  = tid >> 5;
    const int lane = tid & 31;
    const int wm   = wid & 1;
    const int wn   = wid >> 1;
    const int gr   = lane >> 2;
    const int tig  = lane & 3;
    const int bm   = blockIdx.y * 128;
    const int bn   = blockIdx.x * 128;

    const int aRow0 = tid >> 2;
    const int aKc   = (tid & 3) * 4;
    const int bK0   = tid >> 5;
    const int bNc   = (tid & 31) * 4;

    const float* Ap0 = A + (size_t)(bm + aRow0)      * K + aKc;
    const float* Ap1 = A + (size_t)(bm + aRow0 + 64) * K + aKc;
    const float* Bp0 = Bm + (size_t)bK0       * N + bn + bNc;
    const float* Bp1 = Bm + (size_t)(bK0 + 8) * N + bn + bNc;

    float acc[4][4][4];
#pragma unroll
    for (int i = 0; i < 4; ++i)
#pragma unroll
        for (int j = 0; j < 4; ++j)
#pragma unroll
            for (int r = 0; r < 4; ++r) acc[i][j][r] = 0.f;

    const int nstages = K / 16;

    {
        float4 a0 = *(const float4*)(Ap0);
        float4 a1 = *(const float4*)(Ap1);
        float4 b0 = *(const float4*)(Bp0);
        float4 b1 = *(const float4*)(Bp1);
        uint32_t* AsU = (uint32_t*)As[0];
        uint32_t* BsU = (uint32_t*)Bs[0];
        AsU[aRow0*ASTRIDE + aKc + 0] = f2tf32(a0.x);
        AsU[aRow0*ASTRIDE + aKc + 1] = f2tf32(a0.y);
        AsU[aRow0*ASTRIDE + aKc + 2] = f2tf32(a0.z);
        AsU[aRow0*ASTRIDE + aKc + 3] = f2tf32(a0.w);
        AsU[(aRow0+64)*ASTRIDE + aKc + 0] = f2tf32(a1.x);
        AsU[(aRow0+64)*ASTRIDE + aKc + 1] = f2tf32(a1.y);
        AsU[(aRow0+64)*ASTRIDE + aKc + 2] = f2tf32(a1.z);
        AsU[(aRow0+64)*ASTRIDE + aKc + 3] = f2tf32(a1.w);
        BsU[bK0*BSTRIDE + bNc + 0] = f2tf32(b0.x);
        BsU[bK0*BSTRIDE + bNc + 1] = f2tf32(b0.y);
        BsU[bK0*BSTRIDE + bNc + 2] = f2tf32(b0.z);
        BsU[bK0*BSTRIDE + bNc + 3] = f2tf32(b0.w);
        BsU[(bK0+8)*BSTRIDE + bNc + 0] = f2tf32(b1.x);
        BsU[(bK0+8)*BSTRIDE + bNc + 1] = f2tf32(b1.y);
        BsU[(bK0+8)*BSTRIDE + bNc + 2] = f2tf32(b1.z);
        BsU[(bK0+8)*BSTRIDE + bNc + 3] = f2tf32(b1.w);
    }
    __syncthreads();

    int buf = 0;
    for (int s = 0; s < nstages; ++s) {
        float4 a0, a1, b0, b1;
        const bool more = (s + 1 < nstages);
        if (more) {
            const int ko = (s + 1) * 16;
            a0 = *(const float4*)(Ap0 + ko);
            a1 = *(const float4*)(Ap1 + ko);
            b0 = *(const float4*)(Bp0 + (size_t)ko * N);
            b1 = *(const float4*)(Bp1 + (size_t)ko * N);
        }

        const float* Asb = As[buf];
        const float* Bsb = Bs[buf];
#pragma unroll
        for (int ks = 0; ks < 2; ++ks) {
            const int kb = ks * 8;
            uint32_t af[4][4];
#pragma unroll
            for (int mt = 0; mt < 4; ++mt) {
                const int r = wm*64 + mt*16 + gr;
                af[mt][0] = __float_as_uint(Asb[ r     *ASTRIDE + kb + tig    ]);
                af[mt][1] = __float_as_uint(Asb[(r + 8)*ASTRIDE + kb + tig    ]);
                af[mt][2] = __float_as_uint(Asb[ r     *ASTRIDE + kb + tig + 4]);
                af[mt][3] = __float_as_uint(Asb[(r + 8)*ASTRIDE + kb + tig + 4]);
            }
            uint32_t bf[4][2];
#pragma unroll
            for (int nt = 0; nt < 4; ++nt) {
                const int n = wn*32 + nt*8 + gr;
                bf[nt][0] = __float_as_uint(Bsb[(kb + tig    )*BSTRIDE + n]);
                bf[nt][1] = __float_as_uint(Bsb[(kb + tig + 4)*BSTRIDE + n]);
            }
#pragma unroll
            for (int mt = 0; mt < 4; ++mt)
#pragma unroll
                for (int nt = 0; nt < 4; ++nt)
                    mma_tf32(acc[mt][nt][0], acc[mt][nt][1],
                             acc[mt][nt][2], acc[mt][nt][3],
                             af[mt][0], af[mt][1], af[mt][2], af[mt][3],
                             bf[nt][0], bf[nt][1]);
        }

        if (more) {
            __syncthreads();
            const int nb = buf ^ 1;
            uint32_t* AsU = (uint32_t*)As[nb];
            uint32_t* BsU = (uint32_t*)Bs[nb];
            AsU[aRow0*ASTRIDE + aKc + 0] = f2tf32(a0.x);
            AsU[aRow0*ASTRIDE + aKc + 1] = f2tf32(a0.y);
            AsU[aRow0*ASTRIDE + aKc + 2] = f2tf32(a0.z);
            AsU[aRow0*ASTRIDE + aKc + 3] = f2tf32(a0.w);
            AsU[(aRow0+64)*ASTRIDE + aKc + 0] = f2tf32(a1.x);
            AsU[(aRow0+64)*ASTRIDE + aKc + 1] = f2tf32(a1.y);
            AsU[(aRow0+64)*ASTRIDE + aKc + 2] = f2tf32(a1.z);
            AsU[(aRow0+64)*ASTRIDE + aKc + 3] = f2tf32(a1.w);
            BsU[bK0*BSTRIDE + bNc + 0] = f2tf32(b0.x);
            BsU[bK0*BSTRIDE + bNc + 1] = f2tf32(b0.y);
            BsU[bK0*BSTRIDE + bNc + 2] = f2tf32(b0.z);
            BsU[bK0*BSTRIDE + bNc + 3] = f2tf32(b0.w);
            BsU[(bK0+8)*BSTRIDE + bNc + 0] = f2tf32(b1.x);
            BsU[(bK0+8)*BSTRIDE + bNc + 1] = f2tf32(b1.y);
            BsU[(bK0+8)*BSTRIDE + bNc + 2] = f2tf32(b1.z);
            BsU[(bK0+8)*BSTRIDE + bNc + 3] = f2tf32(b1.w);
            __syncthreads();
            buf = nb;
        }
    }

#pragma unroll
    for (int mt = 0; mt < 4; ++mt) {
#pragma unroll
        for (int nt = 0; nt < 4; ++nt) {
            const int nb2 = bn + wn*32 + nt*8 + 2*tig;
#pragma unroll
            for (int half = 0; half < 2; ++half) {
                const int m = bm + wm*64 + mt*16 + gr + half*8;
                const float v0 = acc[mt][nt][half*2 + 0] + bias[nb2 + 0];
                const float v1 = acc[mt][nt][half*2 + 1] + bias[nb2 + 1];
                if (EPI == 0) {
                    const int which = nb2 / Cz;
                    const int c = nb2 - which * Cz;
                    const int h = c >> 6;
                    const int d = c & 63;
                    const int b = m >> 10;
                    const int t = m & 1023;
                    float* dst = (which == 0) ? g_q : (which == 1) ? g_k : g_v;
                    float2 val = make_float2(v0, v1);
                    *(float2*)&dst[(((size_t)(b*NHz + h) << 10) + t)*HDz + d] = val;
                } else {
                    float2 val = make_float2(v0, v1);
                    *(float2*)&Cout[(size_t)m*N + nb2] = val;
                }
            }
        }
    }
}

// ---------------------------------------------------------------------------
// Flash attention with TF32 tensor cores.
// CTA: 64 queries, tiles of 64 keys, HD=64. 256 threads = 8 warps.
// Warp grid for mma: wm = wid&3 (16-row m-tile), wn = wid>>2 (32-col group).
// smem (tf32 as uint32): Qu[q][73], Ku[d][73], Vu[k][73], Ss[q][73] (f32/tf32)
// ---------------------------------------------------------------------------
#define FPAD 73

__global__ __launch_bounds__(256) void flash_kernel(
    const float* __restrict__ gq, const float* __restrict__ gk,
    const float* __restrict__ gv, float* __restrict__ gy)
{
    extern __shared__ uint32_t smu[];
    uint32_t* Qu = smu;               // [64][FPAD]  A of QK^T (q rows, d cols)
    uint32_t* Ku = Qu + 64*FPAD;      // [64][FPAD]  B of QK^T (d rows, k cols)
    uint32_t* Vu = Ku + 64*FPAD;      // [64][FPAD]  B of PV   (k rows, d cols)
    uint32_t* Su = Vu + 64*FPAD;      // [64][FPAD]  S (f32) then P (tf32)
    float* Ssf = (float*)Su;
    __shared__ float m_s[64], l_s[64], alpha_s[64];

    const int bh  = blockIdx.y;
    const int qb  = blockIdx.x;
    const int tid = threadIdx.x;
    const int wid = tid >> 5, lane = tid & 31;
    const int wm  = wid & 3;          // m-tile (16 rows)
    const int wn  = wid >> 2;         // 0..1 (32-col group)
    const int gr  = lane >> 2;
    const int tig = lane & 3;

    const float scale = 0.125f;

    const float* qbase = gq + ((size_t)bh*Tz + qb*64) * HDz;

    // Load Q (row-major, tf32)
    for (int i = tid; i < 64*16; i += 256) {
        const int q  = i >> 4;
        const int db = (i & 15) * 4;
        float4 v4 = *(const float4*)(qbase + q*HDz + db);
        Qu[q*FPAD + db + 0] = f2tf32(v4.x);
        Qu[q*FPAD + db + 1] = f2tf32(v4.y);
        Qu[q*FPAD + db + 2] = f2tf32(v4.z);
        Qu[q*FPAD + db + 3] = f2tf32(v4.w);
    }
    if (tid < 64) { m_s[tid] = -INFINITY; l_s[tid] = 0.f; }

    // Persistent O accumulators: warp tile 16x32 -> 4 n-tiles x 4 regs
    float O[4][4];
#pragma unroll
    for (int nt = 0; nt < 4; ++nt)
#pragma unroll
        for (int r = 0; r < 4; ++r) O[nt][r] = 0.f;

    const int ntiles = qb + 1;
    for (int kt = 0; kt < ntiles; ++kt) {
        const float* kbase = gk + ((size_t)bh*Tz + kt*64) * HDz;
        const float* vbase = gv + ((size_t)bh*Tz + kt*64) * HDz;

        __syncthreads();  // prior iteration done with Ku/Vu/Su
        for (int i = tid; i < 64*16; i += 256) {
            const int r  = i >> 4;
            const int db = (i & 15) * 4;
            float4 k4 = *(const float4*)(kbase + r*HDz + db);
            Ku[(db+0)*FPAD + r] = f2tf32(k4.x);
            Ku[(db+1)*FPAD + r] = f2tf32(k4.y);
            Ku[(db+2)*FPAD + r] = f2tf32(k4.z);
            Ku[(db+3)*FPAD + r] = f2tf32(k4.w);
            float4 v4 = *(const float4*)(vbase + r*HDz + db);
            Vu[r*FPAD + db + 0] = f2tf32(v4.x);
            Vu[r*FPAD + db + 1] = f2tf32(v4.y);
            Vu[r*FPAD + db + 2] = f2tf32(v4.z);
            Vu[r*FPAD + db + 3] = f2tf32(v4.w);
        }
        __syncthreads();

        // ---- S = Q K^T via mma (64x64x64) ----
        float sacc[4][4];
#pragma unroll
        for (int nt = 0; nt < 4; ++nt)
#pragma unroll
            for (int r = 0; r < 4; ++r) sacc[nt][r] = 0.f;

#pragma unroll
        for (int kb = 0; kb < 64; kb += 8) {
            const int r = wm*16 + gr;
            uint32_t a0 = Qu[ r     *FPAD + kb + tig    ];
            uint32_t a1 = Qu[(r + 8)*FPAD + kb + tig    ];
            uint32_t a2 = Qu[ r     *FPAD + kb + tig + 4];
            uint32_t a3 = Qu[(r + 8)*FPAD + kb + tig + 4];
#pragma unroll
            for (int nt = 0; nt < 4; ++nt) {
                const int n = wn*32 + nt*8 + gr;
                uint32_t b0 = Ku[(kb + tig    )*FPAD + n];
                uint32_t b1 = Ku[(kb + tig + 4)*FPAD + n];
                mma_tf32(sacc[nt][0], sacc[nt][1], sacc[nt][2], sacc[nt][3],
                         a0, a1, a2, a3, b0, b1);
            }
        }

        // Scale + mask + store S (f32) to smem
        const bool diag = (kt == qb);
#pragma unroll
        for (int nt = 0; nt < 4; ++nt) {
            const int col = wn*32 + nt*8 + 2*tig;
#pragma unroll
            for (int half = 0; half < 2; ++half) {
                const int row = wm*16 + gr + half*8;
                float s0 = sacc[nt][half*2 + 0] * scale;
                float s1 = sacc[nt][half*2 + 1] * scale;
                if (diag) {
                    if (col     > row) s0 = -INFINITY;
                    if (col + 1 > row) s1 = -INFINITY;
                }
                Ssf[row*FPAD + col    ] = s0;
                Ssf[row*FPAD + col + 1] = s1;
            }
        }
        __syncthreads();

        // ---- Online softmax (rows via warps); writes P as tf32 bits ----
#pragma unroll
        for (int rr = 0; rr < 8; ++rr) {
            const int r = wid*8 + rr;
            float s0 = Ssf[r*FPAD + lane];
            float s1 = Ssf[r*FPAD + 32 + lane];
            float mx = fmaxf(s0, s1);
#pragma unroll
            for (int off = 16; off > 0; off >>= 1)
                mx = fmaxf(mx, __shfl_xor_sync(0xffffffffu, mx, off));
            const float mprev = m_s[r];
            const float mnew  = fmaxf(mprev, mx);
            const float p0 = __expf(s0 - mnew);
            const float p1 = __expf(s1 - mnew);
            Su[r*FPAD + lane]      = f2tf32(p0);
            Su[r*FPAD + 32 + lane] = f2tf32(p1);
            float sum = p0 + p1;
#pragma unroll
            for (int off = 16; off > 0; off >>= 1)
                sum += __shfl_xor_sync(0xffffffffu, sum, off);
            if (lane == 0) {
                const float al = __expf(mprev - mnew);
                alpha_s[r] = al;
                l_s[r] = l_s[r]*al + sum;
                m_s[r] = mnew;
            }
        }
        __syncthreads();

        // ---- O = O*alpha + P V via mma ----
        {
            const int r = wm*16 + gr;
            const float al0 = alpha_s[r];
            const float al1 = alpha_s[r + 8];
#pragma unroll
            for (int nt = 0; nt < 4; ++nt) {
                O[nt][0] *= al0;  O[nt][1] *= al0;
                O[nt][2] *= al1;  O[nt][3] *= al1;
            }
#pragma unroll
            for (int kb = 0; kb < 64; kb += 8) {
                uint32_t a0 = Su[ r     *FPAD + kb + tig    ];
                uint32_t a1 = Su[(r + 8)*FPAD + kb + tig    ];
                uint32_t a2 = Su[ r     *FPAD + kb + tig + 4];
                uint32_t a3 = Su[(r + 8)*FPAD + kb + tig + 4];
#pragma unroll
                for (int nt = 0; nt < 4; ++nt) {
                    const int n = wn*32 + nt*8 + gr;
                    uint32_t b0 = Vu[(kb + tig    )*FPAD + n];
                    uint32_t b1 = Vu[(kb + tig + 4)*FPAD + n];
                    mma_tf32(O[nt][0], O[nt][1], O[nt][2], O[nt][3],
                             a0, a1, a2, a3, b0, b1);
                }
            }
        }
    }

    // Epilogue: normalize and write
    const int b = bh / NHz;
    const int h = bh % NHz;
    {
        const int r0 = wm*16 + gr;
        const float inv0 = 1.f / l_s[r0];
        const float inv1 = 1.f / l_s[r0 + 8];
#pragma unroll
        for (int nt = 0; nt < 4; ++nt) {
            const int col = wn*32 + nt*8 + 2*tig;
            const int q0 = qb*64 + r0;
            float2 w0 = make_float2(O[nt][0]*inv0, O[nt][1]*inv0);
            float2 w1 = make_float2(O[nt][2]*inv1, O[nt][3]*inv1);
            *(float2*)&gy[((size_t)b*Tz + q0    )*Cz + h*HDz + col] = w0;
            *(float2*)&gy[((size_t)b*Tz + q0 + 8)*Cz + h*HDz + col] = w1;
        }
    }
}

// ---------------------------------------------------------------------------
extern "C" void kernel_launch(void* const* d_in, const int* in_sizes, int n_in,
                              void* d_out, int out_size)
{
    (void)in_sizes; (void)n_in; (void)out_size;
    const float* x      = (const float*)d_in[0];
    const float* w_attn = (const float*)d_in[1];
    const float* b_attn = (const float*)d_in[2];
    const float* w_proj = (const float*)d_in[3];
    const float* b_proj = (const float*)d_in[4];
    float* out = (float*)d_out;

    float *pq, *pk, *pv, *py;
    cudaGetSymbolAddress((void**)&pq, g_q);
    cudaGetSymbolAddress((void**)&pk, g_k);
    cudaGetSymbolAddress((void**)&pv, g_v);
    cudaGetSymbolAddress((void**)&py, g_y);

    const int flash_smem = 4 * 64 * FPAD * (int)sizeof(uint32_t);  // 74,752 B
    cudaFuncSetAttribute(flash_kernel,
                         cudaFuncAttributeMaxDynamicSharedMemorySize,
                         flash_smem);

    // 1) QKV = x @ w_attn + b_attn (tf32), scatter to g_q/g_k/g_v
    {
        dim3 grid(3*Cz/128, Mz/128);
        tgemm_kernel<0><<<grid, 256>>>(x, w_attn, b_attn, nullptr,
                                       Mz, 3*Cz, Cz);
    }
    // 2) Flash attention (tf32 mma) into g_y
    {
        dim3 grid(Tz/64, Bz*NHz);
        flash_kernel<<<grid, 256, flash_smem>>>(pq, pk, pv, py);
    }
    // 3) out = g_y @ w_proj + b_proj (tf32)
    {
        dim3 grid(Cz/128, Mz/128);
        tgemm_kernel<1><<<grid, 256>>>(py, w_proj, b_proj, out,
                                       Mz, Cz, Cz);
    }
}

// round 4
// speedup vs baseline: 3.3558x; 1.3757x over previous
#include <cuda_runtime.h>
#include <math.h>
#include <stdint.h>

// Problem constants
#define Bz 8
#define Tz 1024
#define Cz 768
#define NHz 12
#define HDz 64
#define Mz (Bz*Tz)        // 8192

// Scratch (device globals; no allocation)
__device__ float g_q[Bz*NHz*Tz*HDz];
__device__ float g_k[Bz*NHz*Tz*HDz];
__device__ float g_v[Bz*NHz*Tz*HDz];
__device__ float g_y[Bz*Tz*Cz];

__device__ __forceinline__ uint32_t f2tf32(float f) {
    uint32_t u;
    asm("cvt.rna.tf32.f32 %0, %1;" : "=r"(u) : "f"(f));
    return u;
}

__device__ __forceinline__ void mma_tf32(
    float& d0, float& d1, float& d2, float& d3,
    uint32_t a0, uint32_t a1, uint32_t a2, uint32_t a3,
    uint32_t b0, uint32_t b1)
{
    asm volatile(
        "mma.sync.aligned.m16n8k8.row.col.f32.tf32.tf32.f32 "
        "{%0,%1,%2,%3}, {%4,%5,%6,%7}, {%8,%9}, {%0,%1,%2,%3};\n"
        : "+f"(d0), "+f"(d1), "+f"(d2), "+f"(d3)
        : "r"(a0), "r"(a1), "r"(a2), "r"(a3), "r"(b0), "r"(b1));
}

// ---------------------------------------------------------------------------
// TF32 tensor-core GEMM, 128x128 CTA tile (unchanged from R3).
// ---------------------------------------------------------------------------
#define ASTRIDE 20
#define BSTRIDE 132

template <int EPI>
__global__ __launch_bounds__(256) void tgemm_kernel(
    const float* __restrict__ A, const float* __restrict__ Bm,
    const float* __restrict__ bias, float* __restrict__ Cout,
    int M, int N, int K)
{
    __shared__ float As[2][128*ASTRIDE];
    __shared__ float Bs[2][16*BSTRIDE];

    const int tid  = threadIdx.x;
    const int wid  = tid >> 5;
    const int lane = tid & 31;
    const int wm   = wid & 1;
    const int wn   = wid >> 1;
    const int gr   = lane >> 2;
    const int tig  = lane & 3;
    const int bm   = blockIdx.y * 128;
    const int bn   = blockIdx.x * 128;

    const int aRow0 = tid >> 2;
    const int aKc   = (tid & 3) * 4;
    const int bK0   = tid >> 5;
    const int bNc   = (tid & 31) * 4;

    const float* Ap0 = A + (size_t)(bm + aRow0)      * K + aKc;
    const float* Ap1 = A + (size_t)(bm + aRow0 + 64) * K + aKc;
    const float* Bp0 = Bm + (size_t)bK0       * N + bn + bNc;
    const float* Bp1 = Bm + (size_t)(bK0 + 8) * N + bn + bNc;

    float acc[4][4][4];
#pragma unroll
    for (int i = 0; i < 4; ++i)
#pragma unroll
        for (int j = 0; j < 4; ++j)
#pragma unroll
            for (int r = 0; r < 4; ++r) acc[i][j][r] = 0.f;

    const int nstages = K / 16;

    {
        float4 a0 = *(const float4*)(Ap0);
        float4 a1 = *(const float4*)(Ap1);
        float4 b0 = *(const float4*)(Bp0);
        float4 b1 = *(const float4*)(Bp1);
        uint32_t* AsU = (uint32_t*)As[0];
        uint32_t* BsU = (uint32_t*)Bs[0];
        AsU[aRow0*ASTRIDE + aKc + 0] = f2tf32(a0.x);
        AsU[aRow0*ASTRIDE + aKc + 1] = f2tf32(a0.y);
        AsU[aRow0*ASTRIDE + aKc + 2] = f2tf32(a0.z);
        AsU[aRow0*ASTRIDE + aKc + 3] = f2tf32(a0.w);
        AsU[(aRow0+64)*ASTRIDE + aKc + 0] = f2tf32(a1.x);
        AsU[(aRow0+64)*ASTRIDE + aKc + 1] = f2tf32(a1.y);
        AsU[(aRow0+64)*ASTRIDE + aKc + 2] = f2tf32(a1.z);
        AsU[(aRow0+64)*ASTRIDE + aKc + 3] = f2tf32(a1.w);
        BsU[bK0*BSTRIDE + bNc + 0] = f2tf32(b0.x);
        BsU[bK0*BSTRIDE + bNc + 1] = f2tf32(b0.y);
        BsU[bK0*BSTRIDE + bNc + 2] = f2tf32(b0.z);
        BsU[bK0*BSTRIDE + bNc + 3] = f2tf32(b0.w);
        BsU[(bK0+8)*BSTRIDE + bNc + 0] = f2tf32(b1.x);
        BsU[(bK0+8)*BSTRIDE + bNc + 1] = f2tf32(b1.y);
        BsU[(bK0+8)*BSTRIDE + bNc + 2] = f2tf32(b1.z);
        BsU[(bK0+8)*BSTRIDE + bNc + 3] = f2tf32(b1.w);
    }
    __syncthreads();

    int buf = 0;
    for (int s = 0; s < nstages; ++s) {
        float4 a0, a1, b0, b1;
        const bool more = (s + 1 < nstages);
        if (more) {
            const int ko = (s + 1) * 16;
            a0 = *(const float4*)(Ap0 + ko);
            a1 = *(const float4*)(Ap1 + ko);
            b0 = *(const float4*)(Bp0 + (size_t)ko * N);
            b1 = *(const float4*)(Bp1 + (size_t)ko * N);
        }

        const float* Asb = As[buf];
        const float* Bsb = Bs[buf];
#pragma unroll
        for (int ks = 0; ks < 2; ++ks) {
            const int kb = ks * 8;
            uint32_t af[4][4];
#pragma unroll
            for (int mt = 0; mt < 4; ++mt) {
                const int r = wm*64 + mt*16 + gr;
                af[mt][0] = __float_as_uint(Asb[ r     *ASTRIDE + kb + tig    ]);
                af[mt][1] = __float_as_uint(Asb[(r + 8)*ASTRIDE + kb + tig    ]);
                af[mt][2] = __float_as_uint(Asb[ r     *ASTRIDE + kb + tig + 4]);
                af[mt][3] = __float_as_uint(Asb[(r + 8)*ASTRIDE + kb + tig + 4]);
            }
            uint32_t bf[4][2];
#pragma unroll
            for (int nt = 0; nt < 4; ++nt) {
                const int n = wn*32 + nt*8 + gr;
                bf[nt][0] = __float_as_uint(Bsb[(kb + tig    )*BSTRIDE + n]);
                bf[nt][1] = __float_as_uint(Bsb[(kb + tig + 4)*BSTRIDE + n]);
            }
#pragma unroll
            for (int mt = 0; mt < 4; ++mt)
#pragma unroll
                for (int nt = 0; nt < 4; ++nt)
                    mma_tf32(acc[mt][nt][0], acc[mt][nt][1],
                             acc[mt][nt][2], acc[mt][nt][3],
                             af[mt][0], af[mt][1], af[mt][2], af[mt][3],
                             bf[nt][0], bf[nt][1]);
        }

        if (more) {
            __syncthreads();
            const int nb = buf ^ 1;
            uint32_t* AsU = (uint32_t*)As[nb];
            uint32_t* BsU = (uint32_t*)Bs[nb];
            AsU[aRow0*ASTRIDE + aKc + 0] = f2tf32(a0.x);
            AsU[aRow0*ASTRIDE + aKc + 1] = f2tf32(a0.y);
            AsU[aRow0*ASTRIDE + aKc + 2] = f2tf32(a0.z);
            AsU[aRow0*ASTRIDE + aKc + 3] = f2tf32(a0.w);
            AsU[(aRow0+64)*ASTRIDE + aKc + 0] = f2tf32(a1.x);
            AsU[(aRow0+64)*ASTRIDE + aKc + 1] = f2tf32(a1.y);
            AsU[(aRow0+64)*ASTRIDE + aKc + 2] = f2tf32(a1.z);
            AsU[(aRow0+64)*ASTRIDE + aKc + 3] = f2tf32(a1.w);
            BsU[bK0*BSTRIDE + bNc + 0] = f2tf32(b0.x);
            BsU[bK0*BSTRIDE + bNc + 1] = f2tf32(b0.y);
            BsU[bK0*BSTRIDE + bNc + 2] = f2tf32(b0.z);
            BsU[bK0*BSTRIDE + bNc + 3] = f2tf32(b0.w);
            BsU[(bK0+8)*BSTRIDE + bNc + 0] = f2tf32(b1.x);
            BsU[(bK0+8)*BSTRIDE + bNc + 1] = f2tf32(b1.y);
            BsU[(bK0+8)*BSTRIDE + bNc + 2] = f2tf32(b1.z);
            BsU[(bK0+8)*BSTRIDE + bNc + 3] = f2tf32(b1.w);
            __syncthreads();
            buf = nb;
        }
    }

#pragma unroll
    for (int mt = 0; mt < 4; ++mt) {
#pragma unroll
        for (int nt = 0; nt < 4; ++nt) {
            const int nb2 = bn + wn*32 + nt*8 + 2*tig;
#pragma unroll
            for (int half = 0; half < 2; ++half) {
                const int m = bm + wm*64 + mt*16 + gr + half*8;
                const float v0 = acc[mt][nt][half*2 + 0] + bias[nb2 + 0];
                const float v1 = acc[mt][nt][half*2 + 1] + bias[nb2 + 1];
                if (EPI == 0) {
                    const int which = nb2 / Cz;
                    const int c = nb2 - which * Cz;
                    const int h = c >> 6;
                    const int d = c & 63;
                    const int b = m >> 10;
                    const int t = m & 1023;
                    float* dst = (which == 0) ? g_q : (which == 1) ? g_k : g_v;
                    float2 val = make_float2(v0, v1);
                    *(float2*)&dst[(((size_t)(b*NHz + h) << 10) + t)*HDz + d] = val;
                } else {
                    float2 val = make_float2(v0, v1);
                    *(float2*)&Cout[(size_t)m*N + nb2] = val;
                }
            }
        }
    }
}

// ---------------------------------------------------------------------------
// Flash attention v2: 128 queries/CTA, 8 warps, each warp owns 16 full rows.
// Softmax fully in registers (quad shuffles). P -> A-fragments via shuffles.
// K stored natural [key][d], V stored transposed [d][key], stride 68:
// both B-fragment LDS patterns are bank-conflict-free.
// K/V double-buffered in smem with register-staged prefetch.
// ---------------------------------------------------------------------------
#define KSx 68
#define TILE_WORDS (64*KSx)

__global__ __launch_bounds__(256) void flash2_kernel(
    const float* __restrict__ gq, const float* __restrict__ gk,
    const float* __restrict__ gv, float* __restrict__ gy)
{
    extern __shared__ uint32_t smu[];
    // [buf0 K][buf1 K][buf0 Vt][buf1 Vt]
    uint32_t* Kbuf = smu;
    uint32_t* Vbuf = smu + 2*TILE_WORDS;

    const int bh  = blockIdx.x;              // 0..95
    const int qb  = 7 - blockIdx.y;          // heavy CTAs first
    const int tid = threadIdx.x;
    const int wid = tid >> 5, lane = tid & 31;
    const int gr  = lane >> 2;               // 0..7
    const int tig = lane & 3;                // 0..3

    const int qrow0 = qb*128 + wid*16;       // warp's first query row
    const float scale = 0.125f;

    // ---- Load Q fragments once (16 rows x 64 d per warp) ----
    const float* qbase = gq + ((size_t)bh*Tz + qrow0) * HDz;
    uint32_t qf[8][4];
#pragma unroll
    for (int kb = 0; kb < 8; ++kb) {
        qf[kb][0] = f2tf32(qbase[(size_t)(gr    )*HDz + kb*8 + tig    ]);
        qf[kb][1] = f2tf32(qbase[(size_t)(gr + 8)*HDz + kb*8 + tig    ]);
        qf[kb][2] = f2tf32(qbase[(size_t)(gr    )*HDz + kb*8 + tig + 4]);
        qf[kb][3] = f2tf32(qbase[(size_t)(gr + 8)*HDz + kb*8 + tig + 4]);
    }

    float O[8][4];
#pragma unroll
    for (int nt = 0; nt < 8; ++nt)
#pragma unroll
        for (int r = 0; r < 4; ++r) O[nt][r] = 0.f;
    float m0 = -INFINITY, m1 = -INFINITY, l0 = 0.f, l1 = 0.f;

    const int ntiles = 2*qb + 2;

    // staging geometry: thread covers row sr, cols sc..sc+15
    const int sr = tid >> 2;
    const int sc = (tid & 3) * 16;
    const float* kbase0 = gk + (size_t)bh*Tz*HDz;
    const float* vbase0 = gv + (size_t)bh*Tz*HDz;

    // ---- Prologue: tile 0 into buf 0 ----
    {
        const float* kp = kbase0 + (size_t)sr*HDz + sc;
        const float* vp = vbase0 + (size_t)sr*HDz + sc;
        uint32_t* Kd = Kbuf;
        uint32_t* Vd = Vbuf;
#pragma unroll
        for (int j = 0; j < 4; ++j) {
            float4 k4 = *(const float4*)(kp + j*4);
            uint4 ku = make_uint4(f2tf32(k4.x), f2tf32(k4.y),
                                  f2tf32(k4.z), f2tf32(k4.w));
            *(uint4*)&Kd[sr*KSx + sc + j*4] = ku;
            float4 v4 = *(const float4*)(vp + j*4);
            Vd[(sc + j*4 + 0)*KSx + sr] = f2tf32(v4.x);
            Vd[(sc + j*4 + 1)*KSx + sr] = f2tf32(v4.y);
            Vd[(sc + j*4 + 2)*KSx + sr] = f2tf32(v4.z);
            Vd[(sc + j*4 + 3)*KSx + sr] = f2tf32(v4.w);
        }
    }
    __syncthreads();

    const int srcA = (lane & ~3) | (tig >> 1);
    const int srcB = srcA + 2;

    for (int kt = 0; kt < ntiles; ++kt) {
        const int cur = kt & 1;
        const bool more = (kt + 1 < ntiles);

        // Prefetch next tile to registers
        float4 kx[4], vx[4];
        if (more) {
            const float* kp = kbase0 + ((size_t)(kt+1)*64 + sr)*HDz + sc;
            const float* vp = vbase0 + ((size_t)(kt+1)*64 + sr)*HDz + sc;
#pragma unroll
            for (int j = 0; j < 4; ++j) {
                kx[j] = *(const float4*)(kp + j*4);
                vx[j] = *(const float4*)(vp + j*4);
            }
        }

        // Compute (skip if this warp's rows are entirely above the tile)
        if (kt*64 <= qrow0 + 15) {
            const uint32_t* Ksb = Kbuf + cur*TILE_WORDS;
            const uint32_t* Vsb = Vbuf + cur*TILE_WORDS;

            // S = Q K^T
            float sacc[8][4];
#pragma unroll
            for (int nt = 0; nt < 8; ++nt)
#pragma unroll
                for (int r = 0; r < 4; ++r) sacc[nt][r] = 0.f;

#pragma unroll
            for (int kb = 0; kb < 8; ++kb) {
#pragma unroll
                for (int nt = 0; nt < 8; ++nt) {
                    uint32_t b0 = Ksb[(nt*8 + gr)*KSx + kb*8 + tig    ];
                    uint32_t b1 = Ksb[(nt*8 + gr)*KSx + kb*8 + tig + 4];
                    mma_tf32(sacc[nt][0], sacc[nt][1], sacc[nt][2], sacc[nt][3],
                             qf[kb][0], qf[kb][1], qf[kb][2], qf[kb][3],
                             b0, b1);
                }
            }

            // scale + causal mask
            const bool bnd = (kt*64 + 63 > qrow0);
            if (bnd) {
                const int r0 = qrow0 + gr, r1 = qrow0 + gr + 8;
#pragma unroll
                for (int nt = 0; nt < 8; ++nt) {
                    const int c0 = kt*64 + nt*8 + 2*tig;
                    sacc[nt][0] = (c0     > r0) ? -1e30f : sacc[nt][0]*scale;
                    sacc[nt][1] = (c0 + 1 > r0) ? -1e30f : sacc[nt][1]*scale;
                    sacc[nt][2] = (c0     > r1) ? -1e30f : sacc[nt][2]*scale;
                    sacc[nt][3] = (c0 + 1 > r1) ? -1e30f : sacc[nt][3]*scale;
                }
            } else {
#pragma unroll
                for (int nt = 0; nt < 8; ++nt)
#pragma unroll
                    for (int r = 0; r < 4; ++r) sacc[nt][r] *= scale;
            }

            // register softmax: row max (quad reduce)
            float mx0 = -INFINITY, mx1 = -INFINITY;
#pragma unroll
            for (int nt = 0; nt < 8; ++nt) {
                mx0 = fmaxf(mx0, fmaxf(sacc[nt][0], sacc[nt][1]));
                mx1 = fmaxf(mx1, fmaxf(sacc[nt][2], sacc[nt][3]));
            }
            mx0 = fmaxf(mx0, __shfl_xor_sync(0xffffffffu, mx0, 1));
            mx0 = fmaxf(mx0, __shfl_xor_sync(0xffffffffu, mx0, 2));
            mx1 = fmaxf(mx1, __shfl_xor_sync(0xffffffffu, mx1, 1));
            mx1 = fmaxf(mx1, __shfl_xor_sync(0xffffffffu, mx1, 2));

            const float mn0 = fmaxf(m0, mx0);
            const float mn1 = fmaxf(m1, mx1);
            const float a0 = __expf(m0 - mn0);
            const float a1 = __expf(m1 - mn1);
            m0 = mn0; m1 = mn1;

            float s0 = 0.f, s1 = 0.f;
#pragma unroll
            for (int nt = 0; nt < 8; ++nt) {
                sacc[nt][0] = __expf(sacc[nt][0] - mn0);
                sacc[nt][1] = __expf(sacc[nt][1] - mn0);
                sacc[nt][2] = __expf(sacc[nt][2] - mn1);
                sacc[nt][3] = __expf(sacc[nt][3] - mn1);
                s0 += sacc[nt][0] + sacc[nt][1];
                s1 += sacc[nt][2] + sacc[nt][3];
            }
            s0 += __shfl_xor_sync(0xffffffffu, s0, 1);
            s0 += __shfl_xor_sync(0xffffffffu, s0, 2);
            s1 += __shfl_xor_sync(0xffffffffu, s1, 1);
            s1 += __shfl_xor_sync(0xffffffffu, s1, 2);
            l0 = l0*a0 + s0;
            l1 = l1*a1 + s1;

#pragma unroll
            for (int nt = 0; nt < 8; ++nt) {
                O[nt][0] *= a0;  O[nt][1] *= a0;
                O[nt][2] *= a1;  O[nt][3] *= a1;
            }

            // convert P to tf32 bits in place
#pragma unroll
            for (int nt = 0; nt < 8; ++nt)
#pragma unroll
                for (int r = 0; r < 4; ++r)
                    sacc[nt][r] = __uint_as_float(f2tf32(sacc[nt][r]));

            // O += P V : A-fragments of P via quad shuffles
#pragma unroll
            for (int kb = 0; kb < 8; ++kb) {
                float e, o;
                e = __shfl_sync(0xffffffffu, sacc[kb][0], srcA);
                o = __shfl_sync(0xffffffffu, sacc[kb][1], srcA);
                const uint32_t pa0 = __float_as_uint((tig & 1) ? o : e);
                e = __shfl_sync(0xffffffffu, sacc[kb][2], srcA);
                o = __shfl_sync(0xffffffffu, sacc[kb][3], srcA);
                const uint32_t pa1 = __float_as_uint((tig & 1) ? o : e);
                e = __shfl_sync(0xffffffffu, sacc[kb][0], srcB);
                o = __shfl_sync(0xffffffffu, sacc[kb][1], srcB);
                const uint32_t pa2 = __float_as_uint((tig & 1) ? o : e);
                e = __shfl_sync(0xffffffffu, sacc[kb][2], srcB);
                o = __shfl_sync(0xffffffffu, sacc[kb][3], srcB);
                const uint32_t pa3 = __float_as_uint((tig & 1) ? o : e);

#pragma unroll
                for (int nt = 0; nt < 8; ++nt) {
                    uint32_t b0 = Vsb[(nt*8 + gr)*KSx + kb*8 + tig    ];
                    uint32_t b1 = Vsb[(nt*8 + gr)*KSx + kb*8 + tig + 4];
                    mma_tf32(O[nt][0], O[nt][1], O[nt][2], O[nt][3],
                             pa0, pa1, pa2, pa3, b0, b1);
                }
            }
        }

        __syncthreads();   // everyone done reading buf cur^1 (prev) & cur
        if (more) {
            const int nb = cur ^ 1;
            uint32_t* Kd = Kbuf + nb*TILE_WORDS;
            uint32_t* Vd = Vbuf + nb*TILE_WORDS;
#pragma unroll
            for (int j = 0; j < 4; ++j) {
                uint4 ku = make_uint4(f2tf32(kx[j].x), f2tf32(kx[j].y),
                                      f2tf32(kx[j].z), f2tf32(kx[j].w));
                *(uint4*)&Kd[sr*KSx + sc + j*4] = ku;
                Vd[(sc + j*4 + 0)*KSx + sr] = f2tf32(vx[j].x);
                Vd[(sc + j*4 + 1)*KSx + sr] = f2tf32(vx[j].y);
                Vd[(sc + j*4 + 2)*KSx + sr] = f2tf32(vx[j].z);
                Vd[(sc + j*4 + 3)*KSx + sr] = f2tf32(vx[j].w);
            }
            __syncthreads();
        }
    }

    // Epilogue: normalize, write y[b, q, h*64 + d]
    const int b = bh / NHz;
    const int h = bh % NHz;
    const float inv0 = 1.f / l0;
    const float inv1 = 1.f / l1;
    const int q0 = qrow0 + gr;
#pragma unroll
    for (int nt = 0; nt < 8; ++nt) {
        const int col = nt*8 + 2*tig;
        float2 w0 = make_float2(O[nt][0]*inv0, O[nt][1]*inv0);
        float2 w1 = make_float2(O[nt][2]*inv1, O[nt][3]*inv1);
        *(float2*)&gy[((size_t)b*Tz + q0    )*Cz + h*HDz + col] = w0;
        *(float2*)&gy[((size_t)b*Tz + q0 + 8)*Cz + h*HDz + col] = w1;
    }
}

// ---------------------------------------------------------------------------
extern "C" void kernel_launch(void* const* d_in, const int* in_sizes, int n_in,
                              void* d_out, int out_size)
{
    (void)in_sizes; (void)n_in; (void)out_size;
    const float* x      = (const float*)d_in[0];
    const float* w_attn = (const float*)d_in[1];
    const float* b_attn = (const float*)d_in[2];
    const float* w_proj = (const float*)d_in[3];
    const float* b_proj = (const float*)d_in[4];
    float* out = (float*)d_out;

    float *pq, *pk, *pv, *py;
    cudaGetSymbolAddress((void**)&pq, g_q);
    cudaGetSymbolAddress((void**)&pk, g_k);
    cudaGetSymbolAddress((void**)&pv, g_v);
    cudaGetSymbolAddress((void**)&py, g_y);

    const int flash_smem = 4 * TILE_WORDS * (int)sizeof(uint32_t);  // 69,632 B
    cudaFuncSetAttribute(flash2_kernel,
                         cudaFuncAttributeMaxDynamicSharedMemorySize,
                         flash_smem);

    // 1) QKV = x @ w_attn + b_attn (tf32), scatter to g_q/g_k/g_v
    {
        dim3 grid(3*Cz/128, Mz/128);
        tgemm_kernel<0><<<grid, 256>>>(x, w_attn, b_attn, nullptr,
                                       Mz, 3*Cz, Cz);
    }
    // 2) Flash attention v2 (register softmax) into g_y
    {
        dim3 grid(Bz*NHz, Tz/128);     // (96, 8)
        flash2_kernel<<<grid, 256, flash_smem>>>(pq, pk, pv, py);
    }
    // 3) out = g_y @ w_proj + b_proj (tf32)
    {
        dim3 grid(Cz/128, Mz/128);
        tgemm_kernel<1><<<grid, 256>>>(py, w_proj, b_proj, out,
                                       Mz, Cz, Cz);
    }
}